// round 1
// baseline (speedup 1.0000x reference)
#include <cuda_runtime.h>
#include <math.h>

#define T_TOK 4096
#define D_DIM 768
#define E_EXP 8
#define F_DIM 3072

// Scratch (device globals: allocation-free, graph-safe)
__device__ float g_H[(size_t)T_TOK * F_DIM];      // 50 MB intermediate
__device__ int   g_tok[E_EXP * T_TOK];            // per-expert token lists
__device__ int   g_cnt[E_EXP];
__device__ float g_psel[T_TOK];
__device__ float g_probsum[E_EXP];

__global__ void init_kernel() {
    int i = threadIdx.x;
    if (i < E_EXP) { g_cnt[i] = 0; g_probsum[i] = 0.0f; }
}

// One block per token: logits over 8 experts, softmax, argmax routing.
__global__ void gate_kernel(const float* __restrict__ x,
                            const float* __restrict__ Wg) {
    int t = blockIdx.x;
    const float* xr = x + (size_t)t * D_DIM;
    float acc[E_EXP];
#pragma unroll
    for (int e = 0; e < E_EXP; e++) acc[e] = 0.0f;
    for (int k = threadIdx.x; k < D_DIM; k += 128) {
        float xv = xr[k];
        const float* wr = Wg + k * E_EXP;  // Wg is [D,E] row-major
#pragma unroll
        for (int e = 0; e < E_EXP; e++) acc[e] = fmaf(xv, wr[e], acc[e]);
    }
    __shared__ float red[128][E_EXP];
#pragma unroll
    for (int e = 0; e < E_EXP; e++) red[threadIdx.x][e] = acc[e];
    __syncthreads();
    for (int s = 64; s > 0; s >>= 1) {
        if (threadIdx.x < s) {
#pragma unroll
            for (int e = 0; e < E_EXP; e++)
                red[threadIdx.x][e] += red[threadIdx.x + s][e];
        }
        __syncthreads();
    }
    if (threadIdx.x == 0) {
        float mx = red[0][0]; int best = 0;
#pragma unroll
        for (int e = 1; e < E_EXP; e++)
            if (red[0][e] > mx) { mx = red[0][e]; best = e; }  // strict > : first-tie like jax argmax
        float p[E_EXP]; float s = 0.0f;
#pragma unroll
        for (int e = 0; e < E_EXP; e++) { p[e] = expf(red[0][e] - mx); s += p[e]; }
        float inv = 1.0f / s;
#pragma unroll
        for (int e = 0; e < E_EXP; e++) atomicAdd(&g_probsum[e], p[e] * inv);
        g_psel[t] = p[best] * inv;
        int pos = atomicAdd(&g_cnt[best], 1);
        g_tok[best * T_TOK + pos] = t;
    }
}

__device__ __forceinline__ float gelu_exact(float v) {
    return 0.5f * v * (1.0f + erff(v * 0.70710678118654752440f));
}

// Grouped GEMM1: H[tok, F] = gelu(Xg @ W1[e] + b1[e]).  128x128x8 fp32 tile.
__global__ __launch_bounds__(256, 2)
void ffn1_kernel(const float* __restrict__ x,
                 const float* __restrict__ W1,
                 const float* __restrict__ b1) {
    int e = blockIdx.z;
    int cnt = g_cnt[e];
    int m0 = blockIdx.y * 128;
    if (m0 >= cnt) return;
    int n0 = blockIdx.x * 128;

    __shared__ float As[8][128];
    __shared__ float Bs[8][128];
    __shared__ int   stok[128];

    int tid = threadIdx.x;
    if (tid < 128) {
        int m = m0 + tid;
        stok[tid] = (m < cnt) ? g_tok[e * T_TOK + m] : g_tok[e * T_TOK];
    }
    __syncthreads();

    const float* Wbase = W1 + (size_t)e * D_DIM * F_DIM;  // [D,F] row-major
    int ty = tid >> 4, tx = tid & 15;   // 16x16 threads, 8x8 microtile each

    float acc[8][8];
#pragma unroll
    for (int i = 0; i < 8; i++)
#pragma unroll
        for (int j = 0; j < 8; j++) acc[i][j] = 0.0f;

    int arow = tid >> 1, akq = (tid & 1) * 4;
    int bkr  = tid >> 5, bnq = (tid & 31) * 4;
    const float* arow_ptr = x + (size_t)stok[arow] * D_DIM + akq;

    for (int k0 = 0; k0 < D_DIM; k0 += 8) {
        float4 av = *(const float4*)(arow_ptr + k0);
        float4 bv = *(const float4*)(Wbase + (size_t)(k0 + bkr) * F_DIM + n0 + bnq);
        As[akq + 0][arow] = av.x; As[akq + 1][arow] = av.y;
        As[akq + 2][arow] = av.z; As[akq + 3][arow] = av.w;
        *(float4*)&Bs[bkr][bnq] = bv;
        __syncthreads();
#pragma unroll
        for (int k = 0; k < 8; k++) {
            float a[8], b[8];
            *(float4*)&a[0] = *(const float4*)&As[k][ty * 8];
            *(float4*)&a[4] = *(const float4*)&As[k][ty * 8 + 4];
            *(float4*)&b[0] = *(const float4*)&Bs[k][tx * 8];
            *(float4*)&b[4] = *(const float4*)&Bs[k][tx * 8 + 4];
#pragma unroll
            for (int i = 0; i < 8; i++)
#pragma unroll
                for (int j = 0; j < 8; j++)
                    acc[i][j] = fmaf(a[i], b[j], acc[i][j]);
        }
        __syncthreads();
    }

    const float* brow = b1 + e * F_DIM + n0 + tx * 8;
#pragma unroll
    for (int i = 0; i < 8; i++) {
        int m = m0 + ty * 8 + i;
        if (m >= cnt) continue;
        int t = stok[ty * 8 + i];
        float* Hrow = g_H + (size_t)t * F_DIM + n0 + tx * 8;
#pragma unroll
        for (int j = 0; j < 8; j++)
            Hrow[j] = gelu_exact(acc[i][j] + brow[j]);
    }
}

// Grouped GEMM2: out[tok, D] = psel * (H @ W2[e] + b2[e]).  128x128x8 fp32 tile.
__global__ __launch_bounds__(256, 2)
void ffn2_kernel(const float* __restrict__ W2,
                 const float* __restrict__ b2,
                 float* __restrict__ out) {
    int e = blockIdx.z;
    int cnt = g_cnt[e];
    int m0 = blockIdx.y * 128;
    if (m0 >= cnt) return;
    int n0 = blockIdx.x * 128;

    __shared__ float As[8][128];
    __shared__ float Bs[8][128];
    __shared__ int   stok[128];

    int tid = threadIdx.x;
    if (tid < 128) {
        int m = m0 + tid;
        stok[tid] = (m < cnt) ? g_tok[e * T_TOK + m] : g_tok[e * T_TOK];
    }
    __syncthreads();

    const float* Wbase = W2 + (size_t)e * F_DIM * D_DIM;  // [F,D] row-major
    int ty = tid >> 4, tx = tid & 15;

    float acc[8][8];
#pragma unroll
    for (int i = 0; i < 8; i++)
#pragma unroll
        for (int j = 0; j < 8; j++) acc[i][j] = 0.0f;

    int arow = tid >> 1, akq = (tid & 1) * 4;
    int bkr  = tid >> 5, bnq = (tid & 31) * 4;
    const float* arow_ptr = g_H + (size_t)stok[arow] * F_DIM + akq;

    for (int k0 = 0; k0 < F_DIM; k0 += 8) {
        float4 av = *(const float4*)(arow_ptr + k0);
        float4 bv = *(const float4*)(Wbase + (size_t)(k0 + bkr) * D_DIM + n0 + bnq);
        As[akq + 0][arow] = av.x; As[akq + 1][arow] = av.y;
        As[akq + 2][arow] = av.z; As[akq + 3][arow] = av.w;
        *(float4*)&Bs[bkr][bnq] = bv;
        __syncthreads();
#pragma unroll
        for (int k = 0; k < 8; k++) {
            float a[8], b[8];
            *(float4*)&a[0] = *(const float4*)&As[k][ty * 8];
            *(float4*)&a[4] = *(const float4*)&As[k][ty * 8 + 4];
            *(float4*)&b[0] = *(const float4*)&Bs[k][tx * 8];
            *(float4*)&b[4] = *(const float4*)&Bs[k][tx * 8 + 4];
#pragma unroll
            for (int i = 0; i < 8; i++)
#pragma unroll
                for (int j = 0; j < 8; j++)
                    acc[i][j] = fmaf(a[i], b[j], acc[i][j]);
        }
        __syncthreads();
    }

    const float* brow = b2 + e * D_DIM + n0 + tx * 8;
#pragma unroll
    for (int i = 0; i < 8; i++) {
        int m = m0 + ty * 8 + i;
        if (m >= cnt) continue;
        int t = stok[ty * 8 + i];
        float ps = g_psel[t];
        float* orow = out + (size_t)t * D_DIM + n0 + tx * 8;
#pragma unroll
        for (int j = 0; j < 8; j++)
            orow[j] = ps * (acc[i][j] + brow[j]);
    }
}

__global__ void tail_kernel(float* __restrict__ out, int out_size) {
    const int BSD = T_TOK * D_DIM;  // 3145728
    int i = threadIdx.x;
    if (i == 0 && out_size > BSD) {
        float bl = 0.0f;
#pragma unroll
        for (int e = 0; e < E_EXP; e++)
            bl += (g_probsum[e] / (float)T_TOK) * ((float)g_cnt[e] / (float)T_TOK);
        out[BSD] = (float)E_EXP * bl;
    }
    if (i < E_EXP && out_size >= BSD + 1 + E_EXP)
        out[BSD + 1 + i] = (float)g_cnt[i];
}

extern "C" void kernel_launch(void* const* d_in, const int* in_sizes, int n_in,
                              void* d_out, int out_size) {
    // metadata order: x, input_ids, attention_mask, Wg, W1, b1, W2, b2
    const float* x  = (const float*)d_in[0];
    const float* Wg = (const float*)d_in[3];
    const float* W1 = (const float*)d_in[4];
    const float* b1 = (const float*)d_in[5];
    const float* W2 = (const float*)d_in[6];
    const float* b2 = (const float*)d_in[7];
    float* out = (float*)d_out;

    init_kernel<<<1, 32>>>();
    gate_kernel<<<T_TOK, 128>>>(x, Wg);
    ffn1_kernel<<<dim3(F_DIM / 128, T_TOK / 128, E_EXP), 256>>>(x, W1, b1);
    ffn2_kernel<<<dim3(D_DIM / 128, T_TOK / 128, E_EXP), 256>>>(W2, b2, out);
    tail_kernel<<<1, 32>>>(out, out_size);
}

// round 5
// speedup vs baseline: 2.0401x; 2.0401x over previous
#include <cuda_runtime.h>
#include <cuda_bf16.h>
#include <math.h>
#include <stdint.h>

#define T_TOK 4096
#define D_DIM 768
#define E_EXP 8
#define F_DIM 3072

// ---------------- device scratch (~48.5 MB total) ----------------
__device__ __nv_bfloat16 g_Hh[(size_t)T_TOK * F_DIM];   // 24 MB
__device__ __nv_bfloat16 g_Hl[(size_t)T_TOK * F_DIM];   // 24 MB
__device__ int   g_tok[E_EXP * T_TOK];
__device__ int   g_cnt[E_EXP];
__device__ int   g_off[E_EXP];
__device__ int   g_rowtok[T_TOK];
__device__ float g_psel[T_TOK];
__device__ float g_probsum[E_EXP];

__device__ __forceinline__ uint32_t smem_to_u32(const void* p) {
    uint32_t a;
    asm("{ .reg .u64 t; cvta.to.shared.u64 t, %1; cvt.u32.u64 %0, t; }" : "=r"(a) : "l"(p));
    return a;
}

// ---------------- small kernels ----------------
__global__ void init_kernel() {
    int i = threadIdx.x;
    if (i < E_EXP) { g_cnt[i] = 0; g_probsum[i] = 0.0f; }
}

__global__ void gate_kernel(const float* __restrict__ x, const float* __restrict__ Wg) {
    int t = blockIdx.x;
    const float* xr = x + (size_t)t * D_DIM;
    float acc[E_EXP];
#pragma unroll
    for (int e = 0; e < E_EXP; e++) acc[e] = 0.0f;
    for (int k = threadIdx.x; k < D_DIM; k += 128) {
        float xv = xr[k];
        const float* wr = Wg + k * E_EXP;
#pragma unroll
        for (int e = 0; e < E_EXP; e++) acc[e] = fmaf(xv, wr[e], acc[e]);
    }
    __shared__ float red[128][E_EXP];
#pragma unroll
    for (int e = 0; e < E_EXP; e++) red[threadIdx.x][e] = acc[e];
    __syncthreads();
    for (int s = 64; s > 0; s >>= 1) {
        if (threadIdx.x < s) {
#pragma unroll
            for (int e = 0; e < E_EXP; e++) red[threadIdx.x][e] += red[threadIdx.x + s][e];
        }
        __syncthreads();
    }
    if (threadIdx.x == 0) {
        float mx = red[0][0]; int best = 0;
#pragma unroll
        for (int e = 1; e < E_EXP; e++)
            if (red[0][e] > mx) { mx = red[0][e]; best = e; }
        float p[E_EXP]; float s = 0.0f;
#pragma unroll
        for (int e = 0; e < E_EXP; e++) { p[e] = expf(red[0][e] - mx); s += p[e]; }
        float inv = 1.0f / s;
#pragma unroll
        for (int e = 0; e < E_EXP; e++) atomicAdd(&g_probsum[e], p[e] * inv);
        g_psel[t] = p[best] * inv;
        int pos = atomicAdd(&g_cnt[best], 1);
        g_tok[best * T_TOK + pos] = t;
    }
}

__global__ void offs_kernel() {
    if (threadIdx.x == 0) {
        int s = 0;
#pragma unroll
        for (int e = 0; e < E_EXP; e++) { g_off[e] = s; s += g_cnt[e]; }
    }
}

__global__ void rowtok_kernel() {
    int e = blockIdx.y;
    int i = blockIdx.x * 256 + threadIdx.x;
    if (i < g_cnt[e]) g_rowtok[g_off[e] + i] = g_tok[e * T_TOK + i];
}

// ---------------- HMMA grouped GEMM ----------------
__device__ __forceinline__ void ldsm_x4(uint32_t* r, uint32_t addr) {
    asm volatile("ldmatrix.sync.aligned.m8n8.x4.shared.b16 {%0,%1,%2,%3}, [%4];"
                 : "=r"(r[0]), "=r"(r[1]), "=r"(r[2]), "=r"(r[3]) : "r"(addr));
}
__device__ __forceinline__ void mma_bf16(float* c, const uint32_t* a, const uint32_t* b) {
    asm volatile("mma.sync.aligned.m16n8k16.row.col.f32.bf16.bf16.f32 "
                 "{%0,%1,%2,%3}, {%4,%5,%6,%7}, {%8,%9}, {%0,%1,%2,%3};"
                 : "+f"(c[0]), "+f"(c[1]), "+f"(c[2]), "+f"(c[3])
                 : "r"(a[0]), "r"(a[1]), "r"(a[2]), "r"(a[3]), "r"(b[0]), "r"(b[1]));
}
__device__ __forceinline__ void cp16(uint32_t smem_addr, const void* gptr) {
    asm volatile("cp.async.cg.shared.global [%0], [%1], 16;" :: "r"(smem_addr), "l"(gptr));
}
__device__ __forceinline__ uint32_t sw128(uint32_t bo) { return bo ^ ((bo >> 3) & 0x70); }

__device__ __forceinline__ float gelu_exact(float v) {
    return 0.5f * v * (1.0f + erff(v * 0.70710678118654752440f));
}

// convert 8 fp32 -> bf16 hi/lo uint4 pair, store to swizzled smem
__device__ __forceinline__ void cvt_store8(char* hi_base, char* lo_base, uint32_t bo,
                                           const float* v) {
    __nv_bfloat16 hb[8], lb[8];
#pragma unroll
    for (int j = 0; j < 8; j++) {
        hb[j] = __float2bfloat16(v[j]);
        lb[j] = __float2bfloat16(v[j] - __bfloat162float(hb[j]));
    }
    *(uint4*)(hi_base + bo) = *(const uint4*)hb;
    *(uint4*)(lo_base + bo) = *(const uint4*)lb;
}

// cp.async one [128 x 64] bf16 tile into SW128 smem (128B rows)
__device__ __forceinline__ void cp_tile_bf16(uint32_t dst, const __nv_bfloat16* __restrict__ src,
                                             int stride, int k0, int row0) {
    int t = threadIdx.x;
#pragma unroll
    for (int i = 0; i < 4; i++) {
        int idx = i * 256 + t;
        int r = idx >> 3, c16 = idx & 7;
        int rg = row0 + r;
        if (rg > T_TOK - 1) rg = T_TOK - 1;
        cp16(dst + sw128((uint32_t)(r * 128 + c16 * 16)),
             src + (size_t)rg * stride + k0 + c16 * 8);
    }
}

// BM=128, BN=128, BK=64, 256 threads (2x4 warps, warp tile 64x32).
// FFN1: A = gather rows of x (fp32, convert in-kernel), B = W1 [E][D][F] fp32.
// FFN2: A = g_Hh/g_Hl (bf16, cp.async),              B = W2 [E][F][D] fp32.
template <int KT, int NS, bool FFN1>
__global__ void __launch_bounds__(256, 1) mma_kernel(const float* __restrict__ x,
                                                     const float* __restrict__ W,
                                                     const float* __restrict__ bias,
                                                     float* __restrict__ out) {
    int e = blockIdx.z;
    int cnt = g_cnt[e];
    int mt = blockIdx.y;
    if (mt * 128 >= cnt) return;
    int n0 = blockIdx.x * 128;
    int arow0 = g_off[e] + mt * 128;

    extern __shared__ char smem[];
    const int AT = 128 * 128;            // 16KB per A half (hi or lo)
    const int BT = 128 * 128;
    const int STG = 2 * AT + 2 * BT;     // 64KB per stage
    uint32_t s0u = smem_to_u32(smem);

    int tid = threadIdx.x, wid = tid >> 5, l = tid & 31;
    int wm = wid >> 2, wn = wid & 3;

    // ---- per-thread fill coordinates ----
    int a_kb = tid & 7;
    int tokc[4];
    if (FFN1) {
#pragma unroll
        for (int i = 0; i < 4; i++) {
            int m = mt * 128 + i * 32 + (tid >> 3);
            if (m > cnt - 1) m = cnt - 1;
            tokc[i] = g_tok[e * T_TOK + m];
        }
    }
    // B: n fixed per thread; NOTE the expert offset e*KT*NS (the R4 bug).
    int b_n = tid & 127;
    const float* Wb = W + (size_t)e * KT * NS + n0 + b_n;

    float acc[4][4][4];
#pragma unroll
    for (int i = 0; i < 4; i++)
#pragma unroll
        for (int j = 0; j < 4; j++)
#pragma unroll
            for (int q = 0; q < 4; q++) acc[i][j][q] = 0.0f;

    int a_row = wm * 64 + ((l >> 3) & 1) * 8 + (l & 7);
    int a_kbf = ((l >> 4) & 1) * 16;
    int b_row = wn * 32 + ((l >> 4) & 1) * 8 + (l & 7);
    int b_kbf = ((l >> 3) & 1) * 16;

    const int CH = KT / 64;

    auto fill = [&](int c) {
        char* st = smem + (c & 1) * STG;
        int k0 = c * 64;
        if (FFN1) {
#pragma unroll
            for (int i = 0; i < 4; i++) {
                const float* gp = x + (size_t)tokc[i] * D_DIM + k0 + a_kb * 8;
                float v[8];
                *(float4*)&v[0] = *(const float4*)gp;
                *(float4*)&v[4] = *(const float4*)(gp + 4);
                int m = i * 32 + (tid >> 3);
                cvt_store8(st, st + AT, sw128((uint32_t)(m * 128 + a_kb * 16)), v);
            }
        } else {
            cp_tile_bf16(s0u + (c & 1) * STG,      g_Hh, KT, k0, arow0);
            cp_tile_bf16(s0u + (c & 1) * STG + AT, g_Hl, KT, k0, arow0);
            asm volatile("cp.async.commit_group;" ::: "memory");
        }
#pragma unroll
        for (int i = 0; i < 4; i++) {
            int kb = i * 2 + (tid >> 7);
            const float* gp = Wb + (size_t)(k0 + kb * 8) * NS;
            float v[8];
#pragma unroll
            for (int j = 0; j < 8; j++) v[j] = gp[(size_t)j * NS];
            cvt_store8(st + 2 * AT, st + 2 * AT + BT,
                       sw128((uint32_t)(b_n * 128 + kb * 16)), v);
        }
    };

    fill(0);
    for (int c = 0; c < CH; c++) {
        if (c > 0) __syncthreads();
        if (c + 1 < CH) fill(c + 1);
        if (!FFN1) {
            if (c + 1 < CH) { asm volatile("cp.async.wait_group 1;" ::: "memory"); }
            else            { asm volatile("cp.async.wait_group 0;" ::: "memory"); }
        }
        __syncthreads();
        uint32_t sb = s0u + (c & 1) * STG;
#pragma unroll
        for (int k16 = 0; k16 < 4; k16++) {
            uint32_t ah[4][4], al[4][4], bh[4][2], bl[4][2];
#pragma unroll
            for (int i = 0; i < 4; i++) {
                uint32_t bo = sw128((uint32_t)((a_row + i * 16) * 128 + k16 * 32 + a_kbf));
                ldsm_x4(ah[i], sb + bo);
                ldsm_x4(al[i], sb + AT + bo);
            }
#pragma unroll
            for (int jj = 0; jj < 2; jj++) {
                uint32_t bo = sw128((uint32_t)((b_row + jj * 16) * 128 + k16 * 32 + b_kbf));
                uint32_t rh[4], rl[4];
                ldsm_x4(rh, sb + 2 * AT + bo);
                ldsm_x4(rl, sb + 2 * AT + BT + bo);
                bh[2 * jj][0] = rh[0]; bh[2 * jj][1] = rh[1];
                bh[2 * jj + 1][0] = rh[2]; bh[2 * jj + 1][1] = rh[3];
                bl[2 * jj][0] = rl[0]; bl[2 * jj][1] = rl[1];
                bl[2 * jj + 1][0] = rl[2]; bl[2 * jj + 1][1] = rl[3];
            }
#pragma unroll
            for (int i = 0; i < 4; i++)
#pragma unroll
                for (int j = 0; j < 4; j++) {
                    mma_bf16(acc[i][j], ah[i], bh[j]);
                    mma_bf16(acc[i][j], al[i], bh[j]);
                    mma_bf16(acc[i][j], ah[i], bl[j]);
                }
        }
    }

    // ---- epilogue ----
#pragma unroll
    for (int i = 0; i < 4; i++) {
#pragma unroll
        for (int half = 0; half < 2; half++) {
            int m_local = wm * 64 + i * 16 + (l >> 2) + half * 8;
            if (mt * 128 + m_local >= cnt) continue;
            int row = arow0 + m_local;
            float psel = 0.0f; int tok = 0;
            if (!FFN1) { tok = g_rowtok[row]; psel = g_psel[tok]; }
#pragma unroll
            for (int j = 0; j < 4; j++) {
                int col = n0 + wn * 32 + j * 8 + (l & 3) * 2;
                float v0 = acc[i][j][half * 2 + 0];
                float v1 = acc[i][j][half * 2 + 1];
                if (FFN1) {
                    const float* bp = bias + (size_t)e * F_DIM + col;
                    float g0 = gelu_exact(v0 + bp[0]);
                    float g1 = gelu_exact(v1 + bp[1]);
                    __nv_bfloat16 h0 = __float2bfloat16(g0);
                    __nv_bfloat16 h1 = __float2bfloat16(g1);
                    __nv_bfloat16 l0 = __float2bfloat16(g0 - __bfloat162float(h0));
                    __nv_bfloat16 l1 = __float2bfloat16(g1 - __bfloat162float(h1));
                    *(__nv_bfloat162*)(g_Hh + (size_t)row * F_DIM + col) = __nv_bfloat162{h0, h1};
                    *(__nv_bfloat162*)(g_Hl + (size_t)row * F_DIM + col) = __nv_bfloat162{l0, l1};
                } else {
                    const float* bp = bias + (size_t)e * D_DIM + col;
                    float2 o;
                    o.x = psel * (v0 + bp[0]);
                    o.y = psel * (v1 + bp[1]);
                    *(float2*)(out + (size_t)tok * D_DIM + col) = o;
                }
            }
        }
    }
}

__global__ void tail_kernel(float* __restrict__ out, int out_size) {
    const int BSD = T_TOK * D_DIM;
    int i = threadIdx.x;
    if (i == 0 && out_size > BSD) {
        float bl = 0.0f;
#pragma unroll
        for (int e = 0; e < E_EXP; e++)
            bl += (g_probsum[e] / (float)T_TOK) * ((float)g_cnt[e] / (float)T_TOK);
        out[BSD] = (float)E_EXP * bl;
    }
    if (i < E_EXP && out_size >= BSD + 1 + E_EXP)
        out[BSD + 1 + i] = (float)g_cnt[i];
}

// ---------------- launch ----------------
extern "C" void kernel_launch(void* const* d_in, const int* in_sizes, int n_in,
                              void* d_out, int out_size) {
    const float* x  = (const float*)d_in[0];
    const float* Wg = (const float*)d_in[3];
    const float* W1 = (const float*)d_in[4];
    const float* b1 = (const float*)d_in[5];
    const float* W2 = (const float*)d_in[6];
    const float* b2 = (const float*)d_in[7];
    float* out = (float*)d_out;

    const int SMEM = 2 * (2 * 128 * 128 + 2 * 128 * 128);  // 131072
    cudaFuncSetAttribute((const void*)mma_kernel<D_DIM, F_DIM, true>,
                         cudaFuncAttributeMaxDynamicSharedMemorySize, SMEM);
    cudaFuncSetAttribute((const void*)mma_kernel<F_DIM, D_DIM, false>,
                         cudaFuncAttributeMaxDynamicSharedMemorySize, SMEM);

    init_kernel<<<1, 32>>>();
    gate_kernel<<<T_TOK, 128>>>(x, Wg);
    offs_kernel<<<1, 32>>>();
    rowtok_kernel<<<dim3(T_TOK / 256, E_EXP), 256>>>();
    mma_kernel<D_DIM, F_DIM, true><<<dim3(F_DIM / 128, T_TOK / 128, E_EXP), 256, SMEM>>>(
        x, W1, b1, nullptr);
    mma_kernel<F_DIM, D_DIM, false><<<dim3(D_DIM / 128, T_TOK / 128, E_EXP), 256, SMEM>>>(
        nullptr, W2, b2, out);
    tail_kernel<<<1, 32>>>(out, out_size);
}